// round 17
// baseline (speedup 1.0000x reference)
#include <cuda_runtime.h>
#include <cuda_bf16.h>
#include <math.h>
#include <stdint.h>

#define BT_N 64
#define LQ   256
#define LK   512
#define CDIM 512
#define NH   8
#define HD   64

typedef __nv_bfloat16 bf16;

// ---- device scratch ----
__device__ uint8_t g_qf8 [(size_t)16384 * 512];
__device__ uint8_t g_kvf8[(size_t)32768 * 512];
__device__ uint8_t g_wqf8 [512 * 512];
__device__ uint8_t g_wkvf8[1024 * 512];
__device__ uint8_t g_wmf8 [512 * 512];                    // fp8, x32 prescale
__device__ uint8_t g_qh8 [(size_t)BT_N * NH * LQ * HD];   // fp8, x4 prescale
__device__ uint8_t g_kh8 [(size_t)BT_N * NH * LK * HD];   // fp8, x4 prescale
__device__ bf16    g_vh  [(size_t)BT_N * NH * LK * HD];   // bf16 row-major
__device__ uint8_t g_xm8 [(size_t)BT_N * LQ * CDIM];      // fp8, x16 prescale

// ---------------------------------------------------------------------------
__device__ __forceinline__ unsigned pk(float lo, float hi) {
    unsigned r;
    asm("cvt.rn.bf16x2.f32 %0, %1, %2;" : "=r"(r) : "f"(hi), "f"(lo));
    return r;
}
__device__ __forceinline__ unsigned short pk8(float lo, float hi) {
    unsigned short r;
    asm("cvt.rn.satfinite.e4m3x2.f32 %0, %1, %2;" : "=h"(r) : "f"(hi), "f"(lo));
    return r;
}
__device__ __forceinline__ uint32_t smem_u32(const void* p) {
    uint32_t a;
    asm("{ .reg .u64 t; cvta.to.shared.u64 t, %1; cvt.u32.u64 %0, t; }" : "=r"(a) : "l"(p));
    return a;
}
__device__ __forceinline__ void cp_async16(uint32_t dst, const void* src) {
    asm volatile("cp.async.cg.shared.global [%0], [%1], 16;" :: "r"(dst), "l"(src));
}
__device__ __forceinline__ void cp_commit() { asm volatile("cp.async.commit_group;" ::: "memory"); }
template<int N> __device__ __forceinline__ void cp_wait() { asm volatile("cp.async.wait_group %0;" :: "n"(N) : "memory"); }

__device__ __forceinline__ void ldm_x4(unsigned* r, uint32_t addr) {
    asm volatile("ldmatrix.sync.aligned.m8n8.x4.shared.b16 {%0,%1,%2,%3}, [%4];"
                 : "=r"(r[0]), "=r"(r[1]), "=r"(r[2]), "=r"(r[3]) : "r"(addr));
}
__device__ __forceinline__ void ldm_x4_t(unsigned* r, uint32_t addr) {
    asm volatile("ldmatrix.sync.aligned.m8n8.x4.trans.shared.b16 {%0,%1,%2,%3}, [%4];"
                 : "=r"(r[0]), "=r"(r[1]), "=r"(r[2]), "=r"(r[3]) : "r"(addr));
}

__device__ __forceinline__ void mma16816(float* d, const unsigned* a, unsigned b0, unsigned b1) {
    asm volatile(
        "mma.sync.aligned.m16n8k16.row.col.f32.bf16.bf16.f32 "
        "{%0,%1,%2,%3},{%4,%5,%6,%7},{%8,%9},{%0,%1,%2,%3};"
        : "+f"(d[0]), "+f"(d[1]), "+f"(d[2]), "+f"(d[3])
        : "r"(a[0]), "r"(a[1]), "r"(a[2]), "r"(a[3]), "r"(b0), "r"(b1));
}
__device__ __forceinline__ void mma_f8(float* d, const unsigned* a, unsigned b0, unsigned b1) {
    asm volatile(
        "mma.sync.aligned.m16n8k32.row.col.f32.e4m3.e4m3.f32 "
        "{%0,%1,%2,%3},{%4,%5,%6,%7},{%8,%9},{%0,%1,%2,%3};"
        : "+f"(d[0]), "+f"(d[1]), "+f"(d[2]), "+f"(d[3])
        : "r"(a[0]), "r"(a[1]), "r"(a[2]), "r"(a[3]), "r"(b0), "r"(b1));
}
__device__ __forceinline__ void stg_cs_v2(float* p, float x, float y) {
    asm volatile("st.global.cs.v2.f32 [%0], {%1, %2};" :: "l"(p), "f"(x), "f"(y) : "memory");
}

// ---------------------------------------------------------------------------
// fp32 -> fp8 conversion, 16 elements/thread (4 x LDG.128 -> 1 x STG.128)
// weights prescaled x32
// ---------------------------------------------------------------------------
#define Q16   (16384 * 512 / 16)
#define KV16  (32768 * 512 / 16)
#define WQ16  (512 * 512 / 16)
#define WKV16 (1024 * 512 / 16)
#define WM16  (512 * 512 / 16)
#define ALL16 (Q16 + KV16 + WQ16 + WKV16 + WM16)

__device__ __forceinline__ void conv16_f8(const float* src, uint8_t* dst, int i, float s) {
    float4 a = ((const float4*)src)[4 * i];
    float4 b = ((const float4*)src)[4 * i + 1];
    float4 c = ((const float4*)src)[4 * i + 2];
    float4 d = ((const float4*)src)[4 * i + 3];
    unsigned w0 = (unsigned)pk8(a.x * s, a.y * s) | ((unsigned)pk8(a.z * s, a.w * s) << 16);
    unsigned w1 = (unsigned)pk8(b.x * s, b.y * s) | ((unsigned)pk8(b.z * s, b.w * s) << 16);
    unsigned w2 = (unsigned)pk8(c.x * s, c.y * s) | ((unsigned)pk8(c.z * s, c.w * s) << 16);
    unsigned w3 = (unsigned)pk8(d.x * s, d.y * s) | ((unsigned)pk8(d.z * s, d.w * s) << 16);
    ((uint4*)dst)[i] = make_uint4(w0, w1, w2, w3);
}

__global__ __launch_bounds__(256)
void convert_all(const float* __restrict__ q, const float* __restrict__ kv,
                 const float* __restrict__ wq, const float* __restrict__ wkv,
                 const float* __restrict__ wm) {
    int i = blockIdx.x * blockDim.x + threadIdx.x;
    if (i < Q16)                            conv16_f8(q,   g_qf8,   i, 1.0f);
    else if (i < Q16 + KV16)                conv16_f8(kv,  g_kvf8,  i - Q16, 1.0f);
    else if (i < Q16 + KV16 + WQ16)         conv16_f8(wq,  g_wqf8,  i - Q16 - KV16, 32.0f);
    else if (i < Q16 + KV16 + WQ16 + WKV16) conv16_f8(wkv, g_wkvf8, i - Q16 - KV16 - WQ16, 32.0f);
    else                                    conv16_f8(wm,  g_wmf8,  i - Q16 - KV16 - WQ16 - WKV16, 32.0f);
}

// ---------------------------------------------------------------------------
// Merged FP8 projection GEMM: blocks [0,512) = Q proj, [512,2560) = KV proj.
// CTA 128x128, BK=128B, 3-stage cp.async, 8 warps 2Mx4N, 144B row stride.
// ---------------------------------------------------------------------------
#define GSTAGE 36864
#define GSMEM  (3 * GSTAGE)

__global__ __launch_bounds__(256, 2)
void proj_f8(const float* __restrict__ bq, const float* __restrict__ bkv)
{
    extern __shared__ uint8_t dsm8[];
    __shared__ float sred[512];
    const uint32_t smBase = smem_u32(dsm8);

    const int tid   = threadIdx.x;
    const int lane  = tid & 31;
    const int wid   = tid >> 5;
    const int warpM = wid >> 2;
    const int warpN = wid & 3;
    const int g     = lane >> 2;
    const int t2    = (lane & 3) * 2;
    const int lr    = lane & 15;
    const int lc    = lane >> 4;

    const bool isQ = blockIdx.x < 512;
    int bm, bn;
    const uint8_t *A, *W;
    const float* bias;
    if (isQ) {
        int b = blockIdx.x;
        bn = (b & 3) * 128; bm = (b >> 2) * 128;
        A = g_qf8;  W = g_wqf8;  bias = bq;
    } else {
        int b = blockIdx.x - 512;
        bn = (b & 7) * 128; bm = (b >> 3) * 128;
        A = g_kvf8; W = g_wkvf8; bias = bkv;
    }

    const int lrow = tid >> 3;
    const int lcc  = tid & 7;
    const uint8_t* srcA[4];
    const uint8_t* srcB[4];
    uint32_t dstOff[4];
    #pragma unroll
    for (int it = 0; it < 4; it++) {
        int row = lrow + it * 32;
        srcA[it] = A + (size_t)(bm + row) * CDIM + lcc * 16;
        srcB[it] = W + (size_t)(bn + row) * CDIM + lcc * 16;
        dstOff[it] = (uint32_t)(row * 144 + lcc * 16);
    }

    const uint32_t aoff = (uint32_t)((warpM * 64 + lr) * 144 + lc * 16);
    const uint32_t boff = (uint32_t)((warpN * 32 + lr) * 144 + lc * 16) + 18432;

    auto load_tile = [&](int t, int stage) {
        const uint32_t st = smBase + stage * GSTAGE;
        const int koff = t * 128;
        #pragma unroll
        for (int it = 0; it < 4; it++)
            cp_async16(st + dstOff[it], srcA[it] + koff);
        #pragma unroll
        for (int it = 0; it < 4; it++)
            cp_async16(st + 18432 + dstOff[it], srcB[it] + koff);
    };

    float acc[4][4][4] = {};

    load_tile(0, 0); cp_commit();
    load_tile(1, 1); cp_commit();

    #pragma unroll
    for (int t = 0; t < 4; t++) {
        cp_wait<1>();
        __syncthreads();
        if (t + 2 < 4) load_tile(t + 2, (t + 2) % 3);
        cp_commit();

        const uint32_t sa = smBase + (t % 3) * GSTAGE;
        #pragma unroll
        for (int ks = 0; ks < 4; ks++) {
            const int ko2 = ks * 32;
            unsigned af[4][4], bfm[2][4];
            #pragma unroll
            for (int ma = 0; ma < 4; ma++)
                ldm_x4(af[ma], sa + aoff + ma * 16 * 144 + ko2);
            #pragma unroll
            for (int p = 0; p < 2; p++)
                ldm_x4(bfm[p], sa + boff + p * 16 * 144 + ko2);
            #pragma unroll
            for (int ma = 0; ma < 4; ma++)
                #pragma unroll
                for (int nb = 0; nb < 4; nb++)
                    mma_f8(acc[ma][nb], af[ma],
                           bfm[nb >> 1][nb & 1], bfm[nb >> 1][2 + (nb & 1)]);
        }
    }

    float2 bv[4];
    #pragma unroll
    for (int nb = 0; nb < 4; nb++)
        bv[nb] = *(const float2*)&bias[bn + warpN * 32 + nb * 8 + t2];
    #pragma unroll
    for (int ma = 0; ma < 4; ma++)
        #pragma unroll
        for (int nb = 0; nb < 4; nb++) {
            acc[ma][nb][0] = acc[ma][nb][0] * 0.03125f + bv[nb].x;
            acc[ma][nb][1] = acc[ma][nb][1] * 0.03125f + bv[nb].y;
            acc[ma][nb][2] = acc[ma][nb][2] * 0.03125f + bv[nb].x;
            acc[ma][nb][3] = acc[ma][nb][3] * 0.03125f + bv[nb].y;
        }

    float ssq[4][2];
    #pragma unroll
    for (int ma = 0; ma < 4; ma++)
        #pragma unroll
        for (int h2 = 0; h2 < 2; h2++) {
            float s = 0.f;
            #pragma unroll
            for (int nb = 0; nb < 4; nb++) {
                float x = acc[ma][nb][h2 * 2], y = acc[ma][nb][h2 * 2 + 1];
                s += x * x + y * y;
            }
            s += __shfl_xor_sync(0xffffffffu, s, 1);
            s += __shfl_xor_sync(0xffffffffu, s, 2);
            ssq[ma][h2] = s;
        }
    __syncthreads();
    if ((lane & 3) == 0) {
        #pragma unroll
        for (int ma = 0; ma < 4; ma++)
            #pragma unroll
            for (int h2 = 0; h2 < 2; h2++)
                sred[wid * 64 + ma * 16 + h2 * 8 + g] = ssq[ma][h2];
    }
    __syncthreads();
    #pragma unroll
    for (int ma = 0; ma < 4; ma++)
        #pragma unroll
        for (int h2 = 0; h2 < 2; h2++) {
            int r = ma * 16 + h2 * 8 + g;
            float tot = sred[(wid & ~1) * 64 + r] + sred[((wid & ~1) + 1) * 64 + r];
            float rn = 1.f / fmaxf(sqrtf(tot), 1e-12f);
            int m = bm + warpM * 64 + r;
            #pragma unroll
            for (int nb = 0; nb < 4; nb++) {
                int n = bn + warpN * 32 + nb * 8 + t2;
                float v0 = acc[ma][nb][h2 * 2] * rn;
                float v1 = acc[ma][nb][h2 * 2 + 1] * rn;
                if (isQ) {
                    int bt = m >> 8, lq = m & 255;
                    int h = n >> 6, d = n & 63;
                    *(unsigned short*)&g_qh8[(((size_t)(bt * 8 + h)) * 256 + lq) * 64 + d] =
                        pk8(v0 * 4.f, v1 * 4.f);
                } else {
                    int bt = m >> 9, lk = m & 511;
                    int h = (n >> 6) & 7, d = n & 63;
                    if (n < 512) {
                        *(unsigned short*)&g_kh8[(((size_t)(bt * 8 + h)) * 512 + lk) * 64 + d] =
                            pk8(v0 * 4.f, v1 * 4.f);
                    } else {
                        *(unsigned*)&g_vh[(((size_t)(bt * 8 + h)) * 512 + lk) * 64 + d] = pk(v0, v1);
                    }
                }
            }
        }
}

// ---------------------------------------------------------------------------
// FP8 output GEMM with pipelined shortcut prefetch (proven R16) + st.cs out.
// ---------------------------------------------------------------------------
#define SHORT_OFF 36864

__global__ __launch_bounds__(256, 2)
void out_f8(const float* __restrict__ bias,
            const float* __restrict__ shortcut,
            float* __restrict__ out)
{
    extern __shared__ uint8_t dsm8[];
    const uint32_t smBase = smem_u32(dsm8);

    const int tid   = threadIdx.x;
    const int lane  = tid & 31;
    const int wid   = tid >> 5;
    const int warpM = wid >> 2;
    const int warpN = wid & 3;
    const int g     = lane >> 2;
    const int t2    = (lane & 3) * 2;
    const int lr    = lane & 15;
    const int lc    = lane >> 4;
    const int bm    = blockIdx.y * 128;
    const int bn    = blockIdx.x * 128;

    const uint8_t* A = g_xm8;
    const uint8_t* W = g_wmf8;

    const int lrow = tid >> 3;
    const int lcc  = tid & 7;
    const uint8_t* srcA[4];
    const uint8_t* srcB[4];
    uint32_t dstOff[4];
    #pragma unroll
    for (int it = 0; it < 4; it++) {
        int row = lrow + it * 32;
        srcA[it] = A + (size_t)(bm + row) * CDIM + lcc * 16;
        srcB[it] = W + (size_t)(bn + row) * CDIM + lcc * 16;
        dstOff[it] = (uint32_t)(row * 144 + lcc * 16);
    }

    const uint32_t aoff = (uint32_t)((warpM * 64 + lr) * 144 + lc * 16);
    const uint32_t boff = (uint32_t)((warpN * 32 + lr) * 144 + lc * 16) + 18432;

    auto load_tile = [&](int t, int stage) {
        const uint32_t st = smBase + stage * GSTAGE;
        const int koff = t * 128;
        #pragma unroll
        for (int it = 0; it < 4; it++)
            cp_async16(st + dstOff[it], srcA[it] + koff);
        #pragma unroll
        for (int it = 0; it < 4; it++)
            cp_async16(st + 18432 + dstOff[it], srcB[it] + koff);
    };

    float acc[4][4][4] = {};

    load_tile(0, 0); cp_commit();
    load_tile(1, 1); cp_commit();

    #pragma unroll
    for (int t = 0; t < 4; t++) {
        cp_wait<1>();
        __syncthreads();
        if (t + 2 < 4) {
            load_tile(t + 2, (t + 2) % 3);
        } else if (t == 3) {
            // prefetch shortcut 128x128 fp32 (512B/row = 32 x 16B chunks)
            #pragma unroll
            for (int it = 0; it < 16; it++) {
                int c   = tid + it * 256;     // 0..4095
                int row = c >> 5;             // 0..127
                int cc  = c & 31;             // 0..31
                cp_async16(smBase + SHORT_OFF + row * 528 + cc * 16,
                           shortcut + (size_t)(bm + row) * CDIM + bn + cc * 4);
            }
        }
        cp_commit();

        const uint32_t sa = smBase + (t % 3) * GSTAGE;
        #pragma unroll
        for (int ks = 0; ks < 4; ks++) {
            const int ko2 = ks * 32;
            unsigned af[4][4], bfm[2][4];
            #pragma unroll
            for (int ma = 0; ma < 4; ma++)
                ldm_x4(af[ma], sa + aoff + ma * 16 * 144 + ko2);
            #pragma unroll
            for (int p = 0; p < 2; p++)
                ldm_x4(bfm[p], sa + boff + p * 16 * 144 + ko2);
            #pragma unroll
            for (int ma = 0; ma < 4; ma++)
                #pragma unroll
                for (int nb = 0; nb < 4; nb++)
                    mma_f8(acc[ma][nb], af[ma],
                           bfm[nb >> 1][nb & 1], bfm[nb >> 1][2 + (nb & 1)]);
        }
    }

    cp_wait<0>();
    __syncthreads();

    const float s = 1.0f / 512.0f;   // undo x16 (xm) * x32 (wm)
    float2 bv[4];
    #pragma unroll
    for (int nb = 0; nb < 4; nb++)
        bv[nb] = *(const float2*)&bias[bn + warpN * 32 + nb * 8 + t2];

    #pragma unroll
    for (int ma = 0; ma < 4; ma++)
        #pragma unroll
        for (int h2 = 0; h2 < 2; h2++) {
            int ml = warpM * 64 + ma * 16 + h2 * 8 + g;       // local row
            int m  = bm + ml;
            #pragma unroll
            for (int nb = 0; nb < 4; nb++) {
                int nl = warpN * 32 + nb * 8 + t2;            // local col
                float2 sc2 = *(const float2*)(dsm8 + SHORT_OFF + ml * 528 + nl * 4);
                stg_cs_v2(out + (size_t)m * CDIM + bn + nl,
                          acc[ma][nb][h2 * 2 + 0] * s + bv[nb].x + sc2.x,
                          acc[ma][nb][h2 * 2 + 1] * s + bv[nb].y + sc2.y);
            }
        }
}

// ---------------------------------------------------------------------------
// Attention: fp8 QK^T, bf16 PV (LDSM_T); xm stored fp8 (x16).
// block = (128 q-rows, h, bt), 8 warps, warp 16q x 64k, per-16-key streaming.
// ---------------------------------------------------------------------------
#define ASMEM 53248

__global__ __launch_bounds__(256, 2)
void attn_mixed()
{
    extern __shared__ uint8_t dsm8[];
    const uint32_t smQ = smem_u32(dsm8);
    const uint32_t smK = smQ + 10240;
    const uint32_t smV = smK + 15360;

    const int tid  = threadIdx.x;
    const int lane = tid & 31;
    const int wid  = tid >> 5;
    const int g    = lane >> 2;
    const int t2   = (lane & 3) * 2;
    const int lr   = lane & 15;
    const int lc   = lane >> 4;
    const int qt   = blockIdx.x;
    const int h    = blockIdx.y;
    const int bt   = blockIdx.z;

    const uint8_t* Qg = g_qh8 + (((size_t)(bt * 8 + h)) * 256 + qt * 128) * 64;
    const uint8_t* Kg = g_kh8 + ((size_t)(bt * 8 + h)) * 512 * 64;
    const bf16*    Vg = g_vh  + ((size_t)(bt * 8 + h)) * 512 * 64;

    auto load_kv = [&](int t) {
        const int stage = t % 3;
        const uint32_t kb = smK + stage * 5120;
        const uint32_t vb = smV + stage * 9216;
        {
            int row = tid >> 2, cc = tid & 3;
            cp_async16(kb + row * 80 + cc * 16, Kg + (size_t)(t * 64 + row) * 64 + cc * 16);
        }
        #pragma unroll
        for (int it = 0; it < 2; it++) {
            int c = tid + it * 256;
            int row = c >> 3, cc = c & 7;
            cp_async16(vb + row * 144 + cc * 16, Vg + (size_t)(t * 64 + row) * 64 + cc * 8);
        }
    };

    load_kv(0); cp_commit();
    load_kv(1); cp_commit();

    #pragma unroll
    for (int it = 0; it < 2; it++) {
        int idx = tid + it * 256;
        int row = idx >> 2, cc = idx & 3;
        *(uint4*)(dsm8 + row * 80 + cc * 16) = *(const uint4*)(Qg + (size_t)row * 64 + cc * 16);
    }
    __syncthreads();

    unsigned qf[2][4];
    {
        const uint32_t qo = smQ + (uint32_t)((wid * 16 + lr) * 80 + lc * 16);
        ldm_x4(qf[0], qo);
        ldm_x4(qf[1], qo + 32);
    }

    float oacc[8][4] = {};
    float lsum0 = 0.f, lsum1 = 0.f;
    const float sc = 0.125f * 1.4426950408889634f / 16.0f;

    #pragma unroll
    for (int t = 0; t < 8; t++) {
        cp_wait<1>();
        __syncthreads();
        if (t + 2 < 8) load_kv(t + 2);
        cp_commit();

        const uint32_t kb = smK + (t % 3) * 5120;
        const uint32_t vb = smV + (t % 3) * 9216;

        #pragma unroll
        for (int p = 0; p < 4; p++) {
            float s0[4] = {}, s1[4] = {};
            #pragma unroll
            for (int ka = 0; ka < 2; ka++) {
                unsigned kf[4];
                ldm_x4(kf, kb + (p * 16 + lr) * 80 + lc * 16 + ka * 32);
                mma_f8(s0, qf[ka], kf[0], kf[2]);
                mma_f8(s1, qf[ka], kf[1], kf[3]);
            }
            #pragma unroll
            for (int i = 0; i < 4; i++) {
                float e0, e1;
                asm("ex2.approx.f32 %0, %1;" : "=f"(e0) : "f"(s0[i] * sc));
                asm("ex2.approx.f32 %0, %1;" : "=f"(e1) : "f"(s1[i] * sc));
                s0[i] = e0; s1[i] = e1;
            }
            lsum0 += s0[0] + s0[1] + s1[0] + s1[1];
            lsum1 += s0[2] + s0[3] + s1[2] + s1[3];

            unsigned pf[4];
            pf[0] = pk(s0[0], s0[1]);
            pf[1] = pk(s0[2], s0[3]);
            pf[2] = pk(s1[0], s1[1]);
            pf[3] = pk(s1[2], s1[3]);

            #pragma unroll
            for (int d = 0; d < 4; d++) {
                unsigned vf[4];
                ldm_x4_t(vf, vb + (p * 16 + lr) * 144 + lc * 16 + d * 32);
                mma16816(oacc[2 * d + 0], pf, vf[0], vf[1]);
                mma16816(oacc[2 * d + 1], pf, vf[2], vf[3]);
            }
        }
    }

    lsum0 += __shfl_xor_sync(0xffffffffu, lsum0, 1);
    lsum0 += __shfl_xor_sync(0xffffffffu, lsum0, 2);
    lsum1 += __shfl_xor_sync(0xffffffffu, lsum1, 1);
    lsum1 += __shfl_xor_sync(0xffffffffu, lsum1, 2);
    const float rs0 = 16.0f / lsum0, rs1 = 16.0f / lsum1;   // x16 fp8 prescale

    uint8_t* Og = g_xm8 + ((size_t)bt * 256 + qt * 128) * 512 + h * 64;
    const int r0 = wid * 16 + g;
    #pragma unroll
    for (int nb = 0; nb < 8; nb++) {
        int n = nb * 8 + t2;
        *(unsigned short*)&Og[(size_t)r0 * 512 + n] =
            pk8(oacc[nb][0] * rs0, oacc[nb][1] * rs0);
        *(unsigned short*)&Og[(size_t)(r0 + 8) * 512 + n] =
            pk8(oacc[nb][2] * rs1, oacc[nb][3] * rs1);
    }
}

// ---------------------------------------------------------------------------
extern "C" void kernel_launch(void* const* d_in, const int* in_sizes, int n_in,
                              void* d_out, int out_size)
{
    const float* q   = (const float*)d_in[0];
    const float* kv  = (const float*)d_in[1];
    const float* Wq  = (const float*)d_in[2];
    const float* bq  = (const float*)d_in[3];
    const float* Wkv = (const float*)d_in[4];
    const float* bkv = (const float*)d_in[5];
    const float* Wm  = (const float*)d_in[6];
    const float* bm  = (const float*)d_in[7];
    float* out = (float*)d_out;

    cudaFuncSetAttribute(proj_f8,    cudaFuncAttributeMaxDynamicSharedMemorySize, GSMEM);
    cudaFuncSetAttribute(out_f8,     cudaFuncAttributeMaxDynamicSharedMemorySize, GSMEM);
    cudaFuncSetAttribute(attn_mixed, cudaFuncAttributeMaxDynamicSharedMemorySize, ASMEM);

    convert_all<<<ALL16 / 256, 256>>>(q, kv, Wq, Wkv, Wm);

    proj_f8<<<2560, 256, GSMEM>>>(bq, bkv);
    attn_mixed<<<dim3(2, 8, 64), 256, ASMEM>>>();
    out_f8<<<dim3(4, 128), 256, GSMEM>>>(bm, q, out);
}